// round 1
// baseline (speedup 1.0000x reference)
#include <cuda_runtime.h>
#include <math.h>

// Problem constants
#define B_  4
#define V_  256
#define H_  128
#define H2_ 64
#define L_  3
#define BV_ (B_*V_)              // 1024
#define XN_ (BV_*H_)             // 131072
#define EN_ (B_*V_*V_*H_)        // 33554432 elements (134 MB fp32)

// Scratch (allocation-free: __device__ globals)
__device__ float d_ebuf[EN_];
__device__ float d_etmp[EN_];
__device__ float d_xbuf[XN_];
__device__ float d_Vex[XN_];
__device__ float d_Vnx[XN_];
__device__ float d_Unx[XN_];
__device__ float d_agg[XN_];
__device__ float d_xtmp[XN_];
// [0:128) e-sum, [128:256) e-sumsq  (later overwritten by scale/shift)
// [256:384) x-sum, [384:512) x-sumsq
__device__ float d_stats[512];

// ---------------------------------------------------------------------------
__global__ void zero_stats_kernel() {
    d_stats[threadIdx.x] = 0.f;
}

// x = coord @ W_node + b_node
__global__ void node_embed_kernel(const float* __restrict__ coord,
                                  const float* __restrict__ Wn,
                                  const float* __restrict__ bn) {
    int idx = blockIdx.x * blockDim.x + threadIdx.x;   // XN_
    int h = idx & (H_ - 1);
    int row = idx >> 7;
    const float* c = coord + row * 3;
    d_xbuf[idx] = c[0] * Wn[h] + c[1] * Wn[H_ + h] + c[2] * Wn[2 * H_ + h] + bn[h];
}

// e = concat(ev*Wev + bev, tour*Wec0 + best*Wec1 + bec)
__global__ void edge_embed_kernel(const float* __restrict__ ev,
                                  const float* __restrict__ tour,
                                  const float* __restrict__ btour,
                                  const float* __restrict__ Wev,
                                  const float* __restrict__ bev,
                                  const float* __restrict__ Wec,
                                  const float* __restrict__ bec) {
    int idx4 = blockIdx.x * blockDim.x + threadIdx.x;  // EN_/4
    int h4 = idx4 & 31;
    int edge = idx4 >> 5;
    int h0 = h4 * 4;
    float4 o;
    if (h0 < H2_) {
        float v = ev[edge];
        o.x = v * Wev[h0 + 0] + bev[h0 + 0];
        o.y = v * Wev[h0 + 1] + bev[h0 + 1];
        o.z = v * Wev[h0 + 2] + bev[h0 + 2];
        o.w = v * Wev[h0 + 3] + bev[h0 + 3];
    } else {
        float t = tour[edge], bt = btour[edge];
        int g = h0 - H2_;
        o.x = t * Wec[g + 0] + bt * Wec[H2_ + g + 0] + bec[g + 0];
        o.y = t * Wec[g + 1] + bt * Wec[H2_ + g + 1] + bec[g + 1];
        o.z = t * Wec[g + 2] + bt * Wec[H2_ + g + 2] + bec[g + 2];
        o.w = t * Wec[g + 3] + bt * Wec[H2_ + g + 3] + bec[g + 3];
    }
    reinterpret_cast<float4*>(d_ebuf)[idx4] = o;
}

// out = x @ W + bias   (1024x128 @ 128x128). sel: 0->Vex, 1->Vnx, 2->Unx
__global__ void small_gemm_kernel(const float* __restrict__ W,
                                  const float* __restrict__ bias, int sel) {
    __shared__ float xs[H_];
    int row = blockIdx.x;
    int h = threadIdx.x;
    xs[h] = d_xbuf[row * H_ + h];
    __syncthreads();
    float acc = bias[h];
#pragma unroll 8
    for (int k = 0; k < H_; ++k) acc += xs[k] * W[k * H_ + h];
    float* out = (sel == 0) ? d_Vex : (sel == 1) ? d_Vnx : d_Unx;
    out[row * H_ + h] = acc;
}

// Fused per-(b,i): e_tmp = e@Ue + bUe + Vex_i + Vex_j; gates=sigmoid(e_tmp);
// agg = sum_j g*Vnx / (sum_j g + eps); e-BN sum/sumsq stats; write e_tmp.
__global__ void __launch_bounds__(256) fused_edge_kernel(
        const float* __restrict__ Ue, const float* __restrict__ bUe) {
    extern __shared__ float sm[];
    float* Ue_s = sm;              // 128*128 = 16384 floats
    float* es   = sm + 16384;      // 64*128  = 8192 floats (reused for reduce)

    int bi  = blockIdx.x;          // b*V + i
    int tid = threadIdx.x;
    int th  = tid & 31;            // h-quad index (h = th*4 + c)
    int tj  = tid >> 5;            // warp id = j-group

    // Load Ue into smem (4096 float4)
    {
        const float4* src = reinterpret_cast<const float4*>(Ue);
        float4* dst = reinterpret_cast<float4*>(Ue_s);
#pragma unroll
        for (int t = 0; t < 16; ++t) dst[tid + t * 256] = src[tid + t * 256];
    }

    int b = bi >> 8;
    float4 base = reinterpret_cast<const float4*>(bUe)[th];
    {
        float4 vi = reinterpret_cast<const float4*>(d_Vex + bi * H_)[th];
        base.x += vi.x; base.y += vi.y; base.z += vi.z; base.w += vi.w;
    }
    const float* erow = d_ebuf + (size_t)bi * (V_ * H_);
    const float* VexB = d_Vex + (size_t)b * (V_ * H_);
    const float* VnxB = d_Vnx + (size_t)b * (V_ * H_);
    float* etrow = d_etmp + (size_t)bi * (V_ * H_);

    float num[4]  = {0.f, 0.f, 0.f, 0.f};
    float den[4]  = {0.f, 0.f, 0.f, 0.f};
    float ssum[4] = {0.f, 0.f, 0.f, 0.f};
    float ssq[4]  = {0.f, 0.f, 0.f, 0.f};

    for (int jt = 0; jt < 4; ++jt) {
        __syncthreads();
        {   // load 64x128 e-tile (2048 float4)
            const float4* src =
                reinterpret_cast<const float4*>(erow + (size_t)jt * 64 * H_);
            float4* dst = reinterpret_cast<float4*>(es);
#pragma unroll
            for (int t = 0; t < 8; ++t) dst[tid + t * 256] = src[tid + t * 256];
        }
        __syncthreads();

        float acc[8][4];
#pragma unroll
        for (int m = 0; m < 8; ++m) {
            acc[m][0] = base.x; acc[m][1] = base.y;
            acc[m][2] = base.z; acc[m][3] = base.w;
        }
        const float* arow = es + tj * 8 * H_;
#pragma unroll 8
        for (int k = 0; k < H_; ++k) {
            float4 bf = reinterpret_cast<const float4*>(Ue_s + k * H_)[th];
#pragma unroll
            for (int m = 0; m < 8; ++m) {
                float a = arow[m * H_ + k];
                acc[m][0] += a * bf.x;
                acc[m][1] += a * bf.y;
                acc[m][2] += a * bf.z;
                acc[m][3] += a * bf.w;
            }
        }

        // Epilogue: +Vex_j, sigmoid, agg + BN stats accumulation, store e_tmp
#pragma unroll
        for (int m = 0; m < 8; ++m) {
            int j = jt * 64 + tj * 8 + m;
            float4 vj = reinterpret_cast<const float4*>(VexB + j * H_)[th];
            float4 vn = reinterpret_cast<const float4*>(VnxB + j * H_)[th];
            float4 o;
            float et, g;
            et = acc[m][0] + vj.x; g = 1.f / (1.f + __expf(-et));
            num[0] += g * vn.x; den[0] += g; ssum[0] += et; ssq[0] += et * et; o.x = et;
            et = acc[m][1] + vj.y; g = 1.f / (1.f + __expf(-et));
            num[1] += g * vn.y; den[1] += g; ssum[1] += et; ssq[1] += et * et; o.y = et;
            et = acc[m][2] + vj.z; g = 1.f / (1.f + __expf(-et));
            num[2] += g * vn.z; den[2] += g; ssum[2] += et; ssq[2] += et * et; o.z = et;
            et = acc[m][3] + vj.w; g = 1.f / (1.f + __expf(-et));
            num[3] += g * vn.w; den[3] += g; ssum[3] += et; ssq[3] += et * et; o.w = et;
            reinterpret_cast<float4*>(etrow + (size_t)j * H_)[th] = o;
        }
    }

    // Cross-thread reduce (8 partials per h) via smem, then global
    __syncthreads();
    float* red = es;   // 512 floats: num | den | sum | sumsq
    for (int t = tid; t < 512; t += 256) red[t] = 0.f;
    __syncthreads();
    int h0 = th * 4;
#pragma unroll
    for (int c = 0; c < 4; ++c) {
        atomicAdd(red + h0 + c,       num[c]);
        atomicAdd(red + 128 + h0 + c, den[c]);
        atomicAdd(red + 256 + h0 + c, ssum[c]);
        atomicAdd(red + 384 + h0 + c, ssq[c]);
    }
    __syncthreads();
    if (tid < H_) {
        d_agg[bi * H_ + tid] = red[tid] / (red[128 + tid] + 1e-20f);
        atomicAdd(&d_stats[tid],       red[256 + tid]);
        atomicAdd(&d_stats[128 + tid], red[384 + tid]);
    }
}

// x_tmp = Unx + agg; accumulate x-BN stats
__global__ void xtmp_kernel() {
    int idx = blockIdx.x * blockDim.x + threadIdx.x;   // XN_
    int h = idx & (H_ - 1);
    float v = d_Unx[idx] + d_agg[idx];
    d_xtmp[idx] = v;
    atomicAdd(&d_stats[256 + h], v);
    atomicAdd(&d_stats[384 + h], v * v);
}

// x += relu(bn(x_tmp))
__global__ void xupdate_kernel(const float* __restrict__ gx,
                               const float* __restrict__ bx) {
    int idx = blockIdx.x * blockDim.x + threadIdx.x;   // XN_
    int h = idx & (H_ - 1);
    const float inv = 1.f / (float)BV_;
    float mu  = d_stats[256 + h] * inv;
    float var = d_stats[384 + h] * inv - mu * mu;
    float t = gx[h] * (d_xtmp[idx] - mu) * rsqrtf(var + 1e-5f) + bx[h];
    d_xbuf[idx] += fmaxf(t, 0.f);
}

// Turn e sum/sumsq into scale/shift (in place)
__global__ void finalize_e_kernel(const float* __restrict__ ge,
                                  const float* __restrict__ be) {
    int h = threadIdx.x;
    const float inv = 1.f / (float)(B_ * V_ * V_);
    float mu  = d_stats[h] * inv;
    float var = d_stats[128 + h] * inv - mu * mu;
    float sc = ge[h] * rsqrtf(var + 1e-5f);
    d_stats[h] = sc;
    d_stats[128 + h] = be[h] - mu * sc;
}

// e += relu(e_tmp*scale + shift)
__global__ void eupdate_kernel() {
    int idx4 = blockIdx.x * blockDim.x + threadIdx.x;  // EN_/4
    int h4 = idx4 & 31;
    float4 sc = reinterpret_cast<const float4*>(d_stats)[h4];
    float4 sh = reinterpret_cast<const float4*>(d_stats + 128)[h4];
    float4 et = reinterpret_cast<const float4*>(d_etmp)[idx4];
    float4 e  = reinterpret_cast<const float4*>(d_ebuf)[idx4];
    e.x += fmaxf(et.x * sc.x + sh.x, 0.f);
    e.y += fmaxf(et.y * sc.y + sh.y, 0.f);
    e.z += fmaxf(et.z * sc.z + sh.z, 0.f);
    e.w += fmaxf(et.w * sc.w + sh.w, 0.f);
    reinterpret_cast<float4*>(d_ebuf)[idx4] = e;
}

__global__ void zero_out_kernel(float* out) {
    if (threadIdx.x < B_) out[threadIdx.x] = 0.f;
}

// per (b,v): h = relu(x@W1+b1); v = h@W2 + b2; out[b] += v/V
__global__ void readout_kernel(const float* __restrict__ W1,
                               const float* __restrict__ b1,
                               const float* __restrict__ W2,
                               const float* __restrict__ b2,
                               float* __restrict__ out) {
    __shared__ float xs[H_];
    __shared__ float wred[4];
    int row = blockIdx.x;   // b*V + v
    int tid = threadIdx.x;  // 128
    xs[tid] = d_xbuf[row * H_ + tid];
    __syncthreads();
    float acc = b1[tid];
#pragma unroll 8
    for (int k = 0; k < H_; ++k) acc += xs[k] * W1[k * H_ + tid];
    float v = fmaxf(acc, 0.f) * W2[tid];
#pragma unroll
    for (int o = 16; o > 0; o >>= 1) v += __shfl_down_sync(0xffffffffu, v, o);
    if ((tid & 31) == 0) wred[tid >> 5] = v;
    __syncthreads();
    if (tid == 0) {
        float s = wred[0] + wred[1] + wred[2] + wred[3] + b2[0];
        atomicAdd(&out[row >> 8], s * (1.f / (float)V_));
    }
}

// ---------------------------------------------------------------------------
extern "C" void kernel_launch(void* const* d_in, const int* in_sizes, int n_in,
                              void* d_out, int out_size) {
    const float* xev   = (const float*)d_in[1];
    const float* coord = (const float*)d_in[2];
    const float* tour  = (const float*)d_in[3];
    const float* btour = (const float*)d_in[4];
    const float* Wn    = (const float*)d_in[5];
    const float* bn    = (const float*)d_in[6];
    const float* Wev   = (const float*)d_in[7];
    const float* bev   = (const float*)d_in[8];
    const float* Wec   = (const float*)d_in[9];
    const float* bec   = (const float*)d_in[10];
    const float* Ue    = (const float*)d_in[11];
    const float* bUe   = (const float*)d_in[12];
    const float* Ve    = (const float*)d_in[13];
    const float* bVe   = (const float*)d_in[14];
    const float* Un    = (const float*)d_in[15];
    const float* bUn   = (const float*)d_in[16];
    const float* Vn    = (const float*)d_in[17];
    const float* bVn   = (const float*)d_in[18];
    const float* ge    = (const float*)d_in[19];
    const float* be    = (const float*)d_in[20];
    const float* gx    = (const float*)d_in[21];
    const float* bx    = (const float*)d_in[22];
    const float* W1    = (const float*)d_in[23];
    const float* b1    = (const float*)d_in[24];
    const float* W2    = (const float*)d_in[25];
    const float* b2    = (const float*)d_in[26];
    float* out = (float*)d_out;

    const int SMEM_FUSED = (16384 + 8192) * 4;   // 98304 bytes
    cudaFuncSetAttribute(fused_edge_kernel,
                         cudaFuncAttributeMaxDynamicSharedMemorySize, SMEM_FUSED);

    node_embed_kernel<<<XN_ / 256, 256>>>(coord, Wn, bn);
    edge_embed_kernel<<<EN_ / 4 / 256, 256>>>(xev, tour, btour, Wev, bev, Wec, bec);

    for (int l = 0; l < L_; ++l) {
        zero_stats_kernel<<<1, 512>>>();
        small_gemm_kernel<<<BV_, H_>>>(Ve + l * H_ * H_, bVe + l * H_, 0);
        small_gemm_kernel<<<BV_, H_>>>(Vn + l * H_ * H_, bVn + l * H_, 1);
        small_gemm_kernel<<<BV_, H_>>>(Un + l * H_ * H_, bUn + l * H_, 2);
        fused_edge_kernel<<<BV_, 256, SMEM_FUSED>>>(Ue + l * H_ * H_, bUe + l * H_);
        xtmp_kernel<<<XN_ / 256, 256>>>();
        xupdate_kernel<<<XN_ / 256, 256>>>(gx + l * H_, bx + l * H_);
        finalize_e_kernel<<<1, 128>>>(ge + l * H_, be + l * H_);
        eupdate_kernel<<<EN_ / 4 / 256, 256>>>();
    }

    zero_out_kernel<<<1, 32>>>(out);
    readout_kernel<<<BV_, H_>>>(W1, b1, W2, b2, out);
}

// round 2
// speedup vs baseline: 1.2599x; 1.2599x over previous
#include <cuda_runtime.h>
#include <math.h>

// Problem constants
#define B_  4
#define V_  256
#define H_  128
#define H2_ 64
#define L_  3
#define BV_ (B_*V_)              // 1024
#define XN_ (BV_*H_)             // 131072
#define EN_ (B_*V_*V_*H_)        // 33554432 elements (134 MB fp32)

typedef unsigned long long u64;

// Scratch (allocation-free: __device__ globals)
__device__ float d_ebuf[EN_];
__device__ float d_etmp[EN_];
__device__ float d_xbuf[XN_];
__device__ float d_Vex[XN_];
__device__ float d_Vnx[XN_];
__device__ float d_Unx[XN_];
__device__ float d_xtmp[XN_];
// [0:128) e-sum, [128:256) e-sumsq  (later overwritten by scale/shift)
// [256:384) x-sum, [384:512) x-sumsq
__device__ float d_stats[512];

// ---- f32x2 packed-fp32 helpers (sm_103a FFMA2 path, PTX-only) ------------
__device__ __forceinline__ u64 pk2(float lo, float hi) {
    u64 r; asm("mov.b64 %0, {%1, %2};" : "=l"(r) : "f"(lo), "f"(hi)); return r;
}
__device__ __forceinline__ u64 dup2(float v) {
    u64 r; asm("mov.b64 %0, {%1, %1};" : "=l"(r) : "f"(v)); return r;
}
__device__ __forceinline__ void fma2(u64& d, u64 a, u64 b) {
    asm("fma.rn.f32x2 %0, %1, %2, %0;" : "+l"(d) : "l"(a), "l"(b));
}
__device__ __forceinline__ float2 up2(u64 v) {
    float2 f; asm("mov.b64 {%0, %1}, %2;" : "=f"(f.x), "=f"(f.y) : "l"(v)); return f;
}

// ---------------------------------------------------------------------------
__global__ void zero_stats_kernel() {
    d_stats[threadIdx.x] = 0.f;
}

// x = coord @ W_node + b_node
__global__ void node_embed_kernel(const float* __restrict__ coord,
                                  const float* __restrict__ Wn,
                                  const float* __restrict__ bn) {
    int idx = blockIdx.x * blockDim.x + threadIdx.x;   // XN_
    int h = idx & (H_ - 1);
    int row = idx >> 7;
    const float* c = coord + row * 3;
    d_xbuf[idx] = c[0] * Wn[h] + c[1] * Wn[H_ + h] + c[2] * Wn[2 * H_ + h] + bn[h];
}

// e = concat(ev*Wev + bev, tour*Wec0 + best*Wec1 + bec)
__global__ void edge_embed_kernel(const float* __restrict__ ev,
                                  const float* __restrict__ tour,
                                  const float* __restrict__ btour,
                                  const float* __restrict__ Wev,
                                  const float* __restrict__ bev,
                                  const float* __restrict__ Wec,
                                  const float* __restrict__ bec) {
    int idx4 = blockIdx.x * blockDim.x + threadIdx.x;  // EN_/4
    int h4 = idx4 & 31;
    int edge = idx4 >> 5;
    int h0 = h4 * 4;
    float4 o;
    if (h0 < H2_) {
        float v = ev[edge];
        o.x = v * Wev[h0 + 0] + bev[h0 + 0];
        o.y = v * Wev[h0 + 1] + bev[h0 + 1];
        o.z = v * Wev[h0 + 2] + bev[h0 + 2];
        o.w = v * Wev[h0 + 3] + bev[h0 + 3];
    } else {
        float t = tour[edge], bt = btour[edge];
        int g = h0 - H2_;
        o.x = t * Wec[g + 0] + bt * Wec[H2_ + g + 0] + bec[g + 0];
        o.y = t * Wec[g + 1] + bt * Wec[H2_ + g + 1] + bec[g + 1];
        o.z = t * Wec[g + 2] + bt * Wec[H2_ + g + 2] + bec[g + 2];
        o.w = t * Wec[g + 3] + bt * Wec[H2_ + g + 3] + bec[g + 3];
    }
    reinterpret_cast<float4*>(d_ebuf)[idx4] = o;
}

// Three small GEMMs fused: Vex/Vnx/Unx = x @ {Ve,Vn,Un} + bias  (1024x128 each)
__global__ void small_gemm3_kernel(const float* __restrict__ Ve,
                                   const float* __restrict__ bVe,
                                   const float* __restrict__ Vn,
                                   const float* __restrict__ bVn,
                                   const float* __restrict__ Un,
                                   const float* __restrict__ bUn) {
    __shared__ float xs[H_];
    int row = blockIdx.x;
    int h = threadIdx.x;
    xs[h] = d_xbuf[row * H_ + h];
    __syncthreads();
    float a0 = bVe[h], a1 = bVn[h], a2 = bUn[h];
#pragma unroll 8
    for (int k = 0; k < H_; ++k) {
        float xv = xs[k];
        a0 += xv * Ve[k * H_ + h];
        a1 += xv * Vn[k * H_ + h];
        a2 += xv * Un[k * H_ + h];
    }
    d_Vex[row * H_ + h] = a0;
    d_Vnx[row * H_ + h] = a1;
    d_Unx[row * H_ + h] = a2;
}

// Fused per-(b,i): e_tmp = e@Ue + bUe + Vex_i + Vex_j; gates=sigmoid(e_tmp);
// agg = sum_j g*Vnx / (sum_j g + eps); x_tmp = Unx + agg; e/x BN stats.
__global__ void __launch_bounds__(256) fused_edge_kernel(
        const float* __restrict__ Ue, const float* __restrict__ bUe) {
    extern __shared__ float sm[];
    float* Ue_s = sm;              // 128*128 = 16384 floats
    float* es   = sm + 16384;      // 64*128  = 8192 floats (reused for reduce)

    int bi  = blockIdx.x;          // b*V + i
    int tid = threadIdx.x;
    int th  = tid & 31;            // h-quad index (h = th*4 + c)
    int tj  = tid >> 5;            // warp id = j-group

    // Load Ue into smem (4096 float4)
    {
        const float4* src = reinterpret_cast<const float4*>(Ue);
        float4* dst = reinterpret_cast<float4*>(Ue_s);
#pragma unroll
        for (int t = 0; t < 16; ++t) dst[tid + t * 256] = src[tid + t * 256];
    }

    int b = bi >> 8;
    float4 base = reinterpret_cast<const float4*>(bUe)[th];
    {
        float4 vi = reinterpret_cast<const float4*>(d_Vex + bi * H_)[th];
        base.x += vi.x; base.y += vi.y; base.z += vi.z; base.w += vi.w;
    }
    u64 base01 = pk2(base.x, base.y);
    u64 base23 = pk2(base.z, base.w);

    const float* erow = d_ebuf + (size_t)bi * (V_ * H_);
    const float* VexB = d_Vex + (size_t)b * (V_ * H_);
    const float* VnxB = d_Vnx + (size_t)b * (V_ * H_);
    float* etrow = d_etmp + (size_t)bi * (V_ * H_);

    float num[4]  = {0.f, 0.f, 0.f, 0.f};
    float den[4]  = {0.f, 0.f, 0.f, 0.f};
    float ssum[4] = {0.f, 0.f, 0.f, 0.f};
    float ssq[4]  = {0.f, 0.f, 0.f, 0.f};

    for (int jt = 0; jt < 4; ++jt) {
        __syncthreads();
        {   // load 64x128 e-tile (2048 float4)
            const float4* src =
                reinterpret_cast<const float4*>(erow + (size_t)jt * 64 * H_);
            float4* dst = reinterpret_cast<float4*>(es);
#pragma unroll
            for (int t = 0; t < 8; ++t) dst[tid + t * 256] = src[tid + t * 256];
        }
        __syncthreads();

        u64 a01[8], a23[8];
#pragma unroll
        for (int m = 0; m < 8; ++m) { a01[m] = base01; a23[m] = base23; }

        const float* arow = es + tj * 8 * H_;
#pragma unroll 4
        for (int kk = 0; kk < H_; kk += 4) {
            // vector-load 4 k-values of A for each of the 8 j-rows
            float4 av[8];
#pragma unroll
            for (int m = 0; m < 8; ++m)
                av[m] = *reinterpret_cast<const float4*>(arow + m * H_ + kk);
#pragma unroll
            for (int q = 0; q < 4; ++q) {
                float4 bf = reinterpret_cast<const float4*>(Ue_s + (kk + q) * H_)[th];
                u64 bf01 = pk2(bf.x, bf.y);
                u64 bf23 = pk2(bf.z, bf.w);
#pragma unroll
                for (int m = 0; m < 8; ++m) {
                    float a = (q == 0) ? av[m].x : (q == 1) ? av[m].y
                              : (q == 2) ? av[m].z : av[m].w;
                    u64 da = dup2(a);
                    fma2(a01[m], da, bf01);
                    fma2(a23[m], da, bf23);
                }
            }
        }

        // Epilogue: +Vex_j, sigmoid, agg + BN stats accumulation, store e_tmp
#pragma unroll
        for (int m = 0; m < 8; ++m) {
            int j = jt * 64 + tj * 8 + m;
            float4 vj = reinterpret_cast<const float4*>(VexB + j * H_)[th];
            float4 vn = reinterpret_cast<const float4*>(VnxB + j * H_)[th];
            float2 p01 = up2(a01[m]);
            float2 p23 = up2(a23[m]);
            float4 o;
            float et, g;
            et = p01.x + vj.x; g = 1.f / (1.f + __expf(-et));
            num[0] += g * vn.x; den[0] += g; ssum[0] += et; ssq[0] += et * et; o.x = et;
            et = p01.y + vj.y; g = 1.f / (1.f + __expf(-et));
            num[1] += g * vn.y; den[1] += g; ssum[1] += et; ssq[1] += et * et; o.y = et;
            et = p23.x + vj.z; g = 1.f / (1.f + __expf(-et));
            num[2] += g * vn.z; den[2] += g; ssum[2] += et; ssq[2] += et * et; o.z = et;
            et = p23.y + vj.w; g = 1.f / (1.f + __expf(-et));
            num[3] += g * vn.w; den[3] += g; ssum[3] += et; ssq[3] += et * et; o.w = et;
            reinterpret_cast<float4*>(etrow + (size_t)j * H_)[th] = o;
        }
    }

    // Cross-warp reduce (8 partials per h) via plain smem writes + tree sum
    __syncthreads();
    float* red = es;   // 4096 floats: [num|den|sum|sumsq] x [8 warps][128 h]
    int h0 = th * 4;
#pragma unroll
    for (int c = 0; c < 4; ++c) {
        red[tj * 128 + h0 + c]        = num[c];
        red[1024 + tj * 128 + h0 + c] = den[c];
        red[2048 + tj * 128 + h0 + c] = ssum[c];
        red[3072 + tj * 128 + h0 + c] = ssq[c];
    }
    __syncthreads();
    if (tid < H_) {
        float n = 0.f, d = 0.f, s = 0.f, q = 0.f;
#pragma unroll
        for (int w = 0; w < 8; ++w) {
            n += red[w * 128 + tid];
            d += red[1024 + w * 128 + tid];
            s += red[2048 + w * 128 + tid];
            q += red[3072 + w * 128 + tid];
        }
        float aggv = n / (d + 1e-20f);
        float xt = aggv + d_Unx[bi * H_ + tid];     // fused x_tmp
        d_xtmp[bi * H_ + tid] = xt;
        atomicAdd(&d_stats[tid],       s);
        atomicAdd(&d_stats[128 + tid], q);
        atomicAdd(&d_stats[256 + tid], xt);
        atomicAdd(&d_stats[384 + tid], xt * xt);
    }
}

// x += relu(bn(x_tmp))
__global__ void xupdate_kernel(const float* __restrict__ gx,
                               const float* __restrict__ bx) {
    int idx = blockIdx.x * blockDim.x + threadIdx.x;   // XN_
    int h = idx & (H_ - 1);
    const float inv = 1.f / (float)BV_;
    float mu  = d_stats[256 + h] * inv;
    float var = d_stats[384 + h] * inv - mu * mu;
    float t = gx[h] * (d_xtmp[idx] - mu) * rsqrtf(var + 1e-5f) + bx[h];
    d_xbuf[idx] += fmaxf(t, 0.f);
}

// Turn e sum/sumsq into scale/shift (in place)
__global__ void finalize_e_kernel(const float* __restrict__ ge,
                                  const float* __restrict__ be) {
    int h = threadIdx.x;
    const float inv = 1.f / (float)(B_ * V_ * V_);
    float mu  = d_stats[h] * inv;
    float var = d_stats[128 + h] * inv - mu * mu;
    float sc = ge[h] * rsqrtf(var + 1e-5f);
    d_stats[h] = sc;
    d_stats[128 + h] = be[h] - mu * sc;
}

// e += relu(e_tmp*scale + shift)
__global__ void eupdate_kernel() {
    int idx4 = blockIdx.x * blockDim.x + threadIdx.x;  // EN_/4
    int h4 = idx4 & 31;
    float4 sc = reinterpret_cast<const float4*>(d_stats)[h4];
    float4 sh = reinterpret_cast<const float4*>(d_stats + 128)[h4];
    float4 et = reinterpret_cast<const float4*>(d_etmp)[idx4];
    float4 e  = reinterpret_cast<const float4*>(d_ebuf)[idx4];
    e.x += fmaxf(et.x * sc.x + sh.x, 0.f);
    e.y += fmaxf(et.y * sc.y + sh.y, 0.f);
    e.z += fmaxf(et.z * sc.z + sh.z, 0.f);
    e.w += fmaxf(et.w * sc.w + sh.w, 0.f);
    reinterpret_cast<float4*>(d_ebuf)[idx4] = e;
}

__global__ void zero_out_kernel(float* out) {
    if (threadIdx.x < B_) out[threadIdx.x] = 0.f;
}

// per (b,v): h = relu(x@W1+b1); v = h@W2 + b2; out[b] += v/V
__global__ void readout_kernel(const float* __restrict__ W1,
                               const float* __restrict__ b1,
                               const float* __restrict__ W2,
                               const float* __restrict__ b2,
                               float* __restrict__ out) {
    __shared__ float xs[H_];
    __shared__ float wred[4];
    int row = blockIdx.x;   // b*V + v
    int tid = threadIdx.x;  // 128
    xs[tid] = d_xbuf[row * H_ + tid];
    __syncthreads();
    float acc = b1[tid];
#pragma unroll 8
    for (int k = 0; k < H_; ++k) acc += xs[k] * W1[k * H_ + tid];
    float v = fmaxf(acc, 0.f) * W2[tid];
#pragma unroll
    for (int o = 16; o > 0; o >>= 1) v += __shfl_down_sync(0xffffffffu, v, o);
    if ((tid & 31) == 0) wred[tid >> 5] = v;
    __syncthreads();
    if (tid == 0) {
        float s = wred[0] + wred[1] + wred[2] + wred[3] + b2[0];
        atomicAdd(&out[row >> 8], s * (1.f / (float)V_));
    }
}

// ---------------------------------------------------------------------------
extern "C" void kernel_launch(void* const* d_in, const int* in_sizes, int n_in,
                              void* d_out, int out_size) {
    const float* xev   = (const float*)d_in[1];
    const float* coord = (const float*)d_in[2];
    const float* tour  = (const float*)d_in[3];
    const float* btour = (const float*)d_in[4];
    const float* Wn    = (const float*)d_in[5];
    const float* bn    = (const float*)d_in[6];
    const float* Wev   = (const float*)d_in[7];
    const float* bev   = (const float*)d_in[8];
    const float* Wec   = (const float*)d_in[9];
    const float* bec   = (const float*)d_in[10];
    const float* Ue    = (const float*)d_in[11];
    const float* bUe   = (const float*)d_in[12];
    const float* Ve    = (const float*)d_in[13];
    const float* bVe   = (const float*)d_in[14];
    const float* Un    = (const float*)d_in[15];
    const float* bUn   = (const float*)d_in[16];
    const float* Vn    = (const float*)d_in[17];
    const float* bVn   = (const float*)d_in[18];
    const float* ge    = (const float*)d_in[19];
    const float* be    = (const float*)d_in[20];
    const float* gx    = (const float*)d_in[21];
    const float* bx    = (const float*)d_in[22];
    const float* W1    = (const float*)d_in[23];
    const float* b1    = (const float*)d_in[24];
    const float* W2    = (const float*)d_in[25];
    const float* b2    = (const float*)d_in[26];
    float* out = (float*)d_out;

    const int SMEM_FUSED = (16384 + 8192) * 4;   // 98304 bytes
    cudaFuncSetAttribute(fused_edge_kernel,
                         cudaFuncAttributeMaxDynamicSharedMemorySize, SMEM_FUSED);

    node_embed_kernel<<<XN_ / 256, 256>>>(coord, Wn, bn);
    edge_embed_kernel<<<EN_ / 4 / 256, 256>>>(xev, tour, btour, Wev, bev, Wec, bec);

    for (int l = 0; l < L_; ++l) {
        zero_stats_kernel<<<1, 512>>>();
        small_gemm3_kernel<<<BV_, H_>>>(Ve + l * H_ * H_, bVe + l * H_,
                                        Vn + l * H_ * H_, bVn + l * H_,
                                        Un + l * H_ * H_, bUn + l * H_);
        fused_edge_kernel<<<BV_, 256, SMEM_FUSED>>>(Ue + l * H_ * H_, bUe + l * H_);
        xupdate_kernel<<<XN_ / 256, 256>>>(gx + l * H_, bx + l * H_);
        finalize_e_kernel<<<1, 128>>>(ge + l * H_, be + l * H_);
        eupdate_kernel<<<EN_ / 4 / 256, 256>>>();
    }

    zero_out_kernel<<<1, 32>>>(out);
    readout_kernel<<<BV_, H_>>>(W1, b1, W2, b2, out);
}

// round 5
// speedup vs baseline: 1.4702x; 1.1669x over previous
#include <cuda_runtime.h>
#include <cuda_bf16.h>
#include <math.h>
#include <stdint.h>

// Problem constants
#define B_  4
#define V_  256
#define H_  128
#define H2_ 64
#define L_  3
#define BV_ (B_*V_)              // 1024
#define XN_ (BV_*H_)             // 131072
#define EN_ 33554432             // B*V*V*H
#define UPAD 136                 // padded k-row length (bank-conflict-free LDS)

// Scratch (allocation-free: __device__ globals)
__device__ float d_ebuf[EN_];
__device__ float d_etmp[EN_];
__device__ float d_xbuf[XN_];
__device__ float d_Vex[XN_];
__device__ float d_Vnx[XN_];
__device__ float d_Unx[XN_];
__device__ float d_xtmp[XN_];
// [0:128) e-ssum, [128:256) e-ssq, [256:384) x-sum, [384:512) x-sumsq
// [512:640) e-scale (prev layer), [640:768) e-shift (prev layer)
__device__ __align__(16) float d_stats[768];
// UeT (transposed Ue, row = output h, col = k) hi/lo bf16, padded rows of UPAD
__device__ __align__(16) __nv_bfloat16 d_UeThi[H_ * UPAD];
__device__ __align__(16) __nv_bfloat16 d_UeTlo[H_ * UPAD];

__device__ __forceinline__ uint32_t pkbf(float a, float b) {
    __nv_bfloat162 t;
    t.x = __float2bfloat16_rn(a);
    t.y = __float2bfloat16_rn(b);
    return *reinterpret_cast<uint32_t*>(&t);
}

__device__ __forceinline__ void mma16816(float* d, uint32_t a0, uint32_t a1,
                                         uint32_t a2, uint32_t a3,
                                         uint32_t b0, uint32_t b1) {
    asm volatile(
        "mma.sync.aligned.m16n8k16.row.col.f32.bf16.bf16.f32 "
        "{%0,%1,%2,%3}, {%4,%5,%6,%7}, {%8,%9}, {%0,%1,%2,%3};"
        : "+f"(d[0]), "+f"(d[1]), "+f"(d[2]), "+f"(d[3])
        : "r"(a0), "r"(a1), "r"(a2), "r"(a3), "r"(b0), "r"(b1));
}

// ---------------------------------------------------------------------------
__global__ void zero_stats_kernel() {
    d_stats[threadIdx.x] = 0.f;
}

// x = coord @ W_node + b_node
__global__ void node_embed_kernel(const float* __restrict__ coord,
                                  const float* __restrict__ Wn,
                                  const float* __restrict__ bn) {
    int idx = blockIdx.x * blockDim.x + threadIdx.x;   // XN_
    int h = idx & (H_ - 1);
    int row = idx >> 7;
    const float* c = coord + row * 3;
    d_xbuf[idx] = c[0] * Wn[h] + c[1] * Wn[H_ + h] + c[2] * Wn[2 * H_ + h] + bn[h];
}

// e = concat(ev*Wev + bev, tour*Wec0 + best*Wec1 + bec)   (fp32)
__global__ void edge_embed_kernel(const float* __restrict__ ev,
                                  const float* __restrict__ tour,
                                  const float* __restrict__ btour,
                                  const float* __restrict__ Wev,
                                  const float* __restrict__ bev,
                                  const float* __restrict__ Wec,
                                  const float* __restrict__ bec) {
    int idx4 = blockIdx.x * blockDim.x + threadIdx.x;  // EN_/4
    int h4 = idx4 & 31;
    int edge = idx4 >> 5;
    int h0 = h4 * 4;
    float4 o;
    if (h0 < H2_) {
        float v = ev[edge];
        o.x = v * Wev[h0 + 0] + bev[h0 + 0];
        o.y = v * Wev[h0 + 1] + bev[h0 + 1];
        o.z = v * Wev[h0 + 2] + bev[h0 + 2];
        o.w = v * Wev[h0 + 3] + bev[h0 + 3];
    } else {
        float t = tour[edge], bt = btour[edge];
        int g = h0 - H2_;
        o.x = t * Wec[g + 0] + bt * Wec[H2_ + g + 0] + bec[g + 0];
        o.y = t * Wec[g + 1] + bt * Wec[H2_ + g + 1] + bec[g + 1];
        o.z = t * Wec[g + 2] + bt * Wec[H2_ + g + 2] + bec[g + 2];
        o.w = t * Wec[g + 3] + bt * Wec[H2_ + g + 3] + bec[g + 3];
    }
    reinterpret_cast<float4*>(d_ebuf)[idx4] = o;
}

// Prepare UeT hi/lo split, padded rows (per layer)
__global__ void ue_prep_kernel(const float* __restrict__ Ue) {
    int h = blockIdx.x;     // 128  (output feature = B-fragment n/row)
    int k = threadIdx.x;    // 128
    float f = Ue[k * H_ + h];
    __nv_bfloat16 hi = __float2bfloat16_rn(f);
    float r = f - __bfloat162float(hi);
    d_UeThi[h * UPAD + k] = hi;
    d_UeTlo[h * UPAD + k] = __float2bfloat16_rn(r);
}

// Three small GEMMs fused: Vex/Vnx/Unx = x @ {Ve,Vn,Un} + bias
__global__ void __launch_bounds__(128) small_gemm3_kernel(
        const float* __restrict__ Ve, const float* __restrict__ bVe,
        const float* __restrict__ Vn, const float* __restrict__ bVn,
        const float* __restrict__ Un, const float* __restrict__ bUn) {
    __shared__ float xs[16 * H_];
    int h = threadIdx.x;
    int r0 = blockIdx.x * 16;
    {
        const float4* src = reinterpret_cast<const float4*>(d_xbuf + r0 * H_);
        float4* dst = reinterpret_cast<float4*>(xs);
#pragma unroll
        for (int t = 0; t < 4; ++t) dst[h + t * 128] = src[h + t * 128];
    }
    __syncthreads();
    float a0[16], a1[16], a2[16];
    {
        float v0 = bVe[h], v1 = bVn[h], v2 = bUn[h];
#pragma unroll
        for (int r = 0; r < 16; ++r) { a0[r] = v0; a1[r] = v1; a2[r] = v2; }
    }
    for (int k = 0; k < H_; k += 4) {
        float w0[4], w1[4], w2[4];
#pragma unroll
        for (int q = 0; q < 4; ++q) {
            w0[q] = Ve[(k + q) * H_ + h];
            w1[q] = Vn[(k + q) * H_ + h];
            w2[q] = Un[(k + q) * H_ + h];
        }
#pragma unroll
        for (int r = 0; r < 16; ++r) {
            float4 xv = *reinterpret_cast<const float4*>(xs + r * H_ + k);
            a0[r] += xv.x * w0[0] + xv.y * w0[1] + xv.z * w0[2] + xv.w * w0[3];
            a1[r] += xv.x * w1[0] + xv.y * w1[1] + xv.z * w1[2] + xv.w * w1[3];
            a2[r] += xv.x * w2[0] + xv.y * w2[1] + xv.z * w2[2] + xv.w * w2[3];
        }
    }
#pragma unroll
    for (int r = 0; r < 16; ++r) {
        d_Vex[(r0 + r) * H_ + h] = a0[r];
        d_Vnx[(r0 + r) * H_ + h] = a1[r];
        d_Unx[(r0 + r) * H_ + h] = a2[r];
    }
}

// ---------------------------------------------------------------------------
// Fused edge layer (warp-level bf16 mma.sync, 3-term hi/lo split).
// Per CTA = one (b,i). D[j,h] = sum_k e[j,k]*Ue[k,h], 4 slabs of 64 j.
// Optional inline residual-BN update of e (folds previous layer's eupdate).
// Smem byte offsets:
#define OFF_U    0                         // 34816 UeT hi (128 x UPAD bf16)
#define OFF_UL   34816                     // 34816 UeT lo
#define OFF_E    69632                     // 17408 e-slab hi (64 x UPAD bf16)
#define OFF_EL   87040                     // 17408 e-slab lo
#define OFF_BASE 104448                    // 512   (bUe + Vex_i)
#define OFF_RED  104960                    // 8192  (4 q x 4 wj x 128 h)
#define SMEM_FUSED 113152

__global__ void __launch_bounds__(256, 2) fused_edge_kernel(
        const float* __restrict__ bUe, int apply_bn, int write_e) {
    extern __shared__ char smc[];
    int tid = threadIdx.x, w = tid >> 5, lane = tid & 31;
    int wj = w & 3, wh = w >> 2;
    int bi = blockIdx.x, b = bi >> 8;

    // Copy UeT hi/lo (pre-padded) into smem: 2 x 2176 float4 (34816 B each)
    {
        const float4* s1 = reinterpret_cast<const float4*>(d_UeThi);
        const float4* s2 = reinterpret_cast<const float4*>(d_UeTlo);
        float4* dh = reinterpret_cast<float4*>(smc + OFF_U);
        float4* dl = reinterpret_cast<float4*>(smc + OFF_UL);
        for (int i = tid; i < 2176; i += 256) { dh[i] = s1[i]; dl[i] = s2[i]; }
    }
    if (tid < H_)
        reinterpret_cast<float*>(smc + OFF_BASE)[tid] =
            bUe[tid] + d_Vex[bi * H_ + tid];
    {   // zero reduction scratch
        float* red = reinterpret_cast<float*>(smc + OFF_RED);
        for (int i = tid; i < 2048; i += 256) red[i] = 0.f;
    }

    const float* VexB = d_Vex + (size_t)b * V_ * H_;
    const float* VnxB = d_Vnx + (size_t)b * V_ * H_;
    float* etrow = d_etmp + (size_t)bi * (V_ * H_);

    // Per-thread fragment smem addresses (byte offsets), conflict-free (pad 136)
    const char* Ea = smc + OFF_E + ((size_t)( (lane >> 2) * UPAD + (lane & 3) * 2 )) * 2;
    const char* Ua = smc + OFF_U + ((size_t)( (wh * 64 + (lane >> 2)) * UPAD + (lane & 3) * 2 )) * 2;

    for (int s = 0; s < 4; ++s) {
        __syncthreads();
        // ---- load/convert e slab (optionally applying prev-layer BN residual)
        {
            const float4* esrc = reinterpret_cast<const float4*>(
                d_ebuf + (size_t)bi * V_ * H_ + (size_t)s * 64 * H_);
            const float4* tsrc = reinterpret_cast<const float4*>(
                d_etmp + (size_t)bi * V_ * H_ + (size_t)s * 64 * H_);
            float4* edst = reinterpret_cast<float4*>(
                d_ebuf + (size_t)bi * V_ * H_ + (size_t)s * 64 * H_);
#pragma unroll
            for (int t = 0; t < 8; ++t) {
                int c = tid + t * 256;         // [0, 2048)
                int m = c >> 5;
                int k0 = (c & 31) * 4;
                float4 v = esrc[c];
                if (apply_bn) {
                    float4 et4 = tsrc[c];
                    float4 sc = *reinterpret_cast<const float4*>(d_stats + 512 + k0);
                    float4 sh = *reinterpret_cast<const float4*>(d_stats + 640 + k0);
                    v.x += fmaxf(et4.x * sc.x + sh.x, 0.f);
                    v.y += fmaxf(et4.y * sc.y + sh.y, 0.f);
                    v.z += fmaxf(et4.z * sc.z + sh.z, 0.f);
                    v.w += fmaxf(et4.w * sc.w + sh.w, 0.f);
                    edst[c] = v;
                }
                __nv_bfloat16 hx = __float2bfloat16_rn(v.x);
                __nv_bfloat16 hy = __float2bfloat16_rn(v.y);
                __nv_bfloat16 hz = __float2bfloat16_rn(v.z);
                __nv_bfloat16 hw = __float2bfloat16_rn(v.w);
                uint32_t hi01 = pkbf(v.x, v.y), hi23 = pkbf(v.z, v.w);
                uint32_t lo01 = pkbf(v.x - __bfloat162float(hx),
                                     v.y - __bfloat162float(hy));
                uint32_t lo23 = pkbf(v.z - __bfloat162float(hz),
                                     v.w - __bfloat162float(hw));
                size_t off = ((size_t)m * UPAD + k0) * 2;
                *reinterpret_cast<uint2*>(smc + OFF_E + off) = make_uint2(hi01, hi23);
                *reinterpret_cast<uint2*>(smc + OFF_EL + off) = make_uint2(lo01, lo23);
            }
        }
        __syncthreads();

        // ---- MMA: warp tile = 16 j x 64 h, K = 128, 3 terms
        float acc[8][4];
#pragma unroll
        for (int n = 0; n < 8; ++n)
#pragma unroll
            for (int q = 0; q < 4; ++q) acc[n][q] = 0.f;

        const char* EaS = Ea + (size_t)(wj * 16) * UPAD * 2;
#pragma unroll
        for (int kk = 0; kk < 8; ++kk) {
            int ko = kk * 32;   // bytes (16 bf16)
            uint32_t ah0 = *reinterpret_cast<const uint32_t*>(EaS + ko);
            uint32_t ah1 = *reinterpret_cast<const uint32_t*>(EaS + ko + 8 * UPAD * 2);
            uint32_t ah2 = *reinterpret_cast<const uint32_t*>(EaS + ko + 16);
            uint32_t ah3 = *reinterpret_cast<const uint32_t*>(EaS + ko + 8 * UPAD * 2 + 16);
            uint32_t al0 = *reinterpret_cast<const uint32_t*>(EaS + ko + 17408);
            uint32_t al1 = *reinterpret_cast<const uint32_t*>(EaS + ko + 17408 + 8 * UPAD * 2);
            uint32_t al2 = *reinterpret_cast<const uint32_t*>(EaS + ko + 17408 + 16);
            uint32_t al3 = *reinterpret_cast<const uint32_t*>(EaS + ko + 17408 + 8 * UPAD * 2 + 16);
#pragma unroll
            for (int n = 0; n < 8; ++n) {
                const char* ub = Ua + (size_t)n * 8 * UPAD * 2 + ko;
                uint32_t bh0 = *reinterpret_cast<const uint32_t*>(ub);
                uint32_t bh1 = *reinterpret_cast<const uint32_t*>(ub + 16);
                uint32_t bl0 = *reinterpret_cast<const uint32_t*>(ub + 34816);
                uint32_t bl1 = *reinterpret_cast<const uint32_t*>(ub + 34816 + 16);
                mma16816(acc[n], ah0, ah1, ah2, ah3, bh0, bh1);   // Ehi*Uhi
                mma16816(acc[n], al0, al1, al2, al3, bh0, bh1);   // Elo*Uhi
                mma16816(acc[n], ah0, ah1, ah2, ah3, bl0, bl1);   // Ehi*Ulo
            }
        }

        // ---- epilogue on fragments
        int jr0 = s * 64 + wj * 16 + (lane >> 2);
        int jr1 = jr0 + 8;
        float* red = reinterpret_cast<float*>(smc + OFF_RED);
#pragma unroll
        for (int n = 0; n < 8; ++n) {
            int h0 = wh * 64 + n * 8 + (lane & 3) * 2;
            float2 bse = *reinterpret_cast<const float2*>(smc + OFF_BASE + h0 * 4);
            float2 vx0 = *reinterpret_cast<const float2*>(VexB + jr0 * H_ + h0);
            float2 vx1 = *reinterpret_cast<const float2*>(VexB + jr1 * H_ + h0);
            float2 vn0 = *reinterpret_cast<const float2*>(VnxB + jr0 * H_ + h0);
            float2 vn1 = *reinterpret_cast<const float2*>(VnxB + jr1 * H_ + h0);
            float et00 = acc[n][0] + bse.x + vx0.x;
            float et01 = acc[n][1] + bse.y + vx0.y;
            float et10 = acc[n][2] + bse.x + vx1.x;
            float et11 = acc[n][3] + bse.y + vx1.y;
            float g00 = 1.f / (1.f + __expf(-et00));
            float g01 = 1.f / (1.f + __expf(-et01));
            float g10 = 1.f / (1.f + __expf(-et10));
            float g11 = 1.f / (1.f + __expf(-et11));
            float pn0 = g00 * vn0.x + g10 * vn1.x;
            float pn1 = g01 * vn0.y + g11 * vn1.y;
            float pd0 = g00 + g10, pd1 = g01 + g11;
#pragma unroll
            for (int o = 4; o < 32; o <<= 1) {
                pn0 += __shfl_xor_sync(0xffffffffu, pn0, o);
                pn1 += __shfl_xor_sync(0xffffffffu, pn1, o);
                pd0 += __shfl_xor_sync(0xffffffffu, pd0, o);
                pd1 += __shfl_xor_sync(0xffffffffu, pd1, o);
            }
            if (lane < 4) {
                int hr = wh * 64 + n * 8 + lane * 2;
                red[wj * 128 + hr]          += pn0;
                red[wj * 128 + hr + 1]      += pn1;
                red[512 + wj * 128 + hr]    += pd0;
                red[512 + wj * 128 + hr + 1]+= pd1;
            }
            if (write_e) {
                float ps0 = et00 + et10, ps1 = et01 + et11;
                float pq0 = et00 * et00 + et10 * et10;
                float pq1 = et01 * et01 + et11 * et11;
#pragma unroll
                for (int o = 4; o < 32; o <<= 1) {
                    ps0 += __shfl_xor_sync(0xffffffffu, ps0, o);
                    ps1 += __shfl_xor_sync(0xffffffffu, ps1, o);
                    pq0 += __shfl_xor_sync(0xffffffffu, pq0, o);
                    pq1 += __shfl_xor_sync(0xffffffffu, pq1, o);
                }
                if (lane < 4) {
                    int hr = wh * 64 + n * 8 + lane * 2;
                    red[1024 + wj * 128 + hr]          += ps0;
                    red[1024 + wj * 128 + hr + 1]      += ps1;
                    red[1536 + wj * 128 + hr]          += pq0;
                    red[1536 + wj * 128 + hr + 1]      += pq1;
                }
                *reinterpret_cast<float2*>(etrow + (size_t)jr0 * H_ + h0) =
                    make_float2(et00, et01);
                *reinterpret_cast<float2*>(etrow + (size_t)jr1 * H_ + h0) =
                    make_float2(et10, et11);
            }
        }
    }

    __syncthreads();
    if (tid < H_) {
        const float* red = reinterpret_cast<const float*>(smc + OFF_RED);
        float n = 0.f, d = 0.f;
#pragma unroll
        for (int q = 0; q < 4; ++q) {
            n += red[q * 128 + tid];
            d += red[512 + q * 128 + tid];
        }
        float aggv = n / (d + 1e-20f);
        float xt = aggv + d_Unx[bi * H_ + tid];
        d_xtmp[bi * H_ + tid] = xt;
        atomicAdd(&d_stats[256 + tid], xt);
        atomicAdd(&d_stats[384 + tid], xt * xt);
        if (write_e) {
            float ss = 0.f, qq = 0.f;
#pragma unroll
            for (int q = 0; q < 4; ++q) {
                ss += red[1024 + q * 128 + tid];
                qq += red[1536 + q * 128 + tid];
            }
            atomicAdd(&d_stats[tid], ss);
            atomicAdd(&d_stats[128 + tid], qq);
        }
    }
}

// x += relu(bn(x_tmp))
__global__ void xupdate_kernel(const float* __restrict__ gx,
                               const float* __restrict__ bx) {
    int idx = blockIdx.x * blockDim.x + threadIdx.x;   // XN_
    int h = idx & (H_ - 1);
    const float inv = 1.f / (float)BV_;
    float mu  = d_stats[256 + h] * inv;
    float var = d_stats[384 + h] * inv - mu * mu;
    float t = gx[h] * (d_xtmp[idx] - mu) * rsqrtf(var + 1e-5f) + bx[h];
    d_xbuf[idx] += fmaxf(t, 0.f);
}

// Turn e sum/sumsq into scale/shift (slots 512/640)
__global__ void finalize_e_kernel(const float* __restrict__ ge,
                                  const float* __restrict__ be) {
    int h = threadIdx.x;
    const float inv = 1.f / (float)(B_ * V_ * V_);
    float mu  = d_stats[h] * inv;
    float var = d_stats[128 + h] * inv - mu * mu;
    float sc = ge[h] * rsqrtf(var + 1e-5f);
    d_stats[512 + h] = sc;
    d_stats[640 + h] = be[h] - mu * sc;
}

__global__ void zero_out_kernel(float* out) {
    if (threadIdx.x < B_) out[threadIdx.x] = 0.f;
}

// per (b,v): h = relu(x@W1+b1); v = h@W2 + b2; out[b] += v/V
__global__ void readout_kernel(const float* __restrict__ W1,
                               const float* __restrict__ b1,
                               const float* __restrict__ W2,
                               const float* __restrict__ b2,
                               float* __restrict__ out) {
    __shared__ float xs[H_];
    __shared__ float wred[4];
    int row = blockIdx.x;   // b*V + v
    int tid = threadIdx.x;  // 128
    xs[tid] = d_xbuf[row * H_ + tid];
    __syncthreads();
    float acc = b1[tid];
#pragma unroll 8
    for (int k = 0; k < H_; ++k) acc += xs[k] * W1[k * H_ + tid];
    float v = fmaxf(acc, 0.f) * W2[tid];
#pragma unroll
    for (int o = 16; o > 0; o >>= 1) v += __shfl_down_sync(0xffffffffu, v, o);
    if ((tid & 31) == 0) wred[tid >> 5] = v;
    __syncthreads();
    if (tid == 0) {
        float s = wred[0] + wred[1] + wred[2] + wred[3] + b2[0];
        atomicAdd(&out[row >> 8], s * (1.f / (float)V_));
    }
}

// ---------------------------------------------------------------------------
extern "C" void kernel_launch(void* const* d_in, const int* in_sizes, int n_in,
                              void* d_out, int out_size) {
    const float* xev   = (const float*)d_in[1];
    const float* coord = (const float*)d_in[2];
    const float* tour  = (const float*)d_in[3];
    const float* btour = (const float*)d_in[4];
    const float* Wn    = (const float*)d_in[5];
    const float* bn    = (const float*)d_in[6];
    const float* Wev   = (const float*)d_in[7];
    const float* bev   = (const float*)d_in[8];
    const float* Wec   = (const float*)d_in[9];
    const float* bec   = (const float*)d_in[10];
    const float* Ue    = (const float*)d_in[11];
    const float* bUe   = (const float*)d_in[12];
    const float* Ve    = (const float*)d_in[13];
    const float* bVe   = (const float*)d_in[14];
    const float* Un    = (const float*)d_in[15];
    const float* bUn   = (const float*)d_in[16];
    const float* Vn    = (const float*)d_in[17];
    const float* bVn   = (const float*)d_in[18];
    const float* ge    = (const float*)d_in[19];
    const float* be    = (const float*)d_in[20];
    const float* gx    = (const float*)d_in[21];
    const float* bx    = (const float*)d_in[22];
    const float* W1    = (const float*)d_in[23];
    const float* b1    = (const float*)d_in[24];
    const float* W2    = (const float*)d_in[25];
    const float* b2    = (const float*)d_in[26];
    float* out = (float*)d_out;

    cudaFuncSetAttribute(fused_edge_kernel,
                         cudaFuncAttributeMaxDynamicSharedMemorySize, SMEM_FUSED);

    node_embed_kernel<<<XN_ / 256, 256>>>(coord, Wn, bn);
    edge_embed_kernel<<<EN_ / 4 / 256, 256>>>(xev, tour, btour, Wev, bev, Wec, bec);

    for (int l = 0; l < L_; ++l) {
        zero_stats_kernel<<<1, 512>>>();
        ue_prep_kernel<<<128, 128>>>(Ue + l * H_ * H_);
        small_gemm3_kernel<<<64, 128>>>(Ve + l * H_ * H_, bVe + l * H_,
                                        Vn + l * H_ * H_, bVn + l * H_,
                                        Un + l * H_ * H_, bUn + l * H_);
        int apply_bn = (l > 0) ? 1 : 0;
        int write_e = (l < L_ - 1) ? 1 : 0;
        fused_edge_kernel<<<BV_, 256, SMEM_FUSED>>>(bUe + l * H_, apply_bn, write_e);
        xupdate_kernel<<<XN_ / 256, 256>>>(gx + l * H_, bx + l * H_);
        if (write_e) finalize_e_kernel<<<1, 128>>>(ge + l * H_, be + l * H_);
    }

    zero_out_kernel<<<1, 32>>>(out);
    readout_kernel<<<BV_, H_>>>(W1, b1, W2, b2, out);
}

// round 6
// speedup vs baseline: 1.8018x; 1.2255x over previous
#include <cuda_runtime.h>
#include <cuda_bf16.h>
#include <math.h>
#include <stdint.h>

// Problem constants
#define B_  4
#define V_  256
#define H_  128
#define H2_ 64
#define L_  3
#define BV_ (B_*V_)              // 1024
#define XN_ (BV_*H_)             // 131072
#define EN_ 33554432             // B*V*V*H

// Scratch (allocation-free: __device__ globals)
// e stored SPLIT: hi/lo bf16 planes (hi+lo reconstructs ~fp32 precision)
__device__ __align__(16) __nv_bfloat16 d_ehi[EN_];
__device__ __align__(16) __nv_bfloat16 d_elo[EN_];
__device__ float d_etmp[EN_];
__device__ float d_xbuf[XN_];
__device__ float d_Vex[XN_];
__device__ float d_Vnx[XN_];
__device__ float d_Unx[XN_];
__device__ float d_xtmp[XN_];
// [0:128) e-ssum, [128:256) e-ssq, [256:384) x-sum, [384:512) x-sumsq
// [512:640) e-scale, [640:768) e-shift
__device__ __align__(16) float d_stats[768];
// UeT (transposed Ue: row = output h, col = k) hi/lo bf16, plain [128][128]
__device__ __align__(16) __nv_bfloat16 d_UeThi[H_ * H_];
__device__ __align__(16) __nv_bfloat16 d_UeTlo[H_ * H_];

// ---- helpers --------------------------------------------------------------
__device__ __forceinline__ void split2(float a, float b, uint32_t& hi, uint32_t& lo) {
    __nv_bfloat162 h2;
    h2.x = __float2bfloat16_rn(a); h2.y = __float2bfloat16_rn(b);
    hi = *reinterpret_cast<uint32_t*>(&h2);
    __nv_bfloat162 l2;
    l2.x = __float2bfloat16_rn(a - __bfloat162float(h2.x));
    l2.y = __float2bfloat16_rn(b - __bfloat162float(h2.y));
    lo = *reinterpret_cast<uint32_t*>(&l2);
}
__device__ __forceinline__ float2 up_bf2(uint32_t u) {
    __nv_bfloat162 t = *reinterpret_cast<__nv_bfloat162*>(&u);
    return make_float2(__bfloat162float(t.x), __bfloat162float(t.y));
}
__device__ __forceinline__ uint32_t s2u(const void* p) {
    uint32_t a;
    asm("{ .reg .u64 t; cvta.to.shared.u64 t, %1; cvt.u32.u64 %0, t; }"
        : "=r"(a) : "l"(p));
    return a;
}
__device__ __forceinline__ void mma16816(float* d, const uint32_t* a,
                                         uint32_t b0, uint32_t b1) {
    asm volatile(
        "mma.sync.aligned.m16n8k16.row.col.f32.bf16.bf16.f32 "
        "{%0,%1,%2,%3}, {%4,%5,%6,%7}, {%8,%9}, {%0,%1,%2,%3};"
        : "+f"(d[0]), "+f"(d[1]), "+f"(d[2]), "+f"(d[3])
        : "r"(a[0]), "r"(a[1]), "r"(a[2]), "r"(a[3]), "r"(b0), "r"(b1));
}
__device__ __forceinline__ void ldsm4(uint32_t addr, uint32_t* r) {
    asm volatile("ldmatrix.sync.aligned.m8n8.x4.shared.b16 {%0,%1,%2,%3}, [%4];"
        : "=r"(r[0]), "=r"(r[1]), "=r"(r[2]), "=r"(r[3]) : "r"(addr));
}
#define CP16(dst, src) \
    asm volatile("cp.async.cg.shared.global [%0], [%1], 16;" :: "r"(dst), "l"(src))
#define CPCOMMIT() asm volatile("cp.async.commit_group;")

// ---------------------------------------------------------------------------
// x = coord @ W_node + b_node
__global__ void node_embed_kernel(const float* __restrict__ coord,
                                  const float* __restrict__ Wn,
                                  const float* __restrict__ bn) {
    int idx = blockIdx.x * blockDim.x + threadIdx.x;
    int h = idx & (H_ - 1);
    int row = idx >> 7;
    const float* c = coord + row * 3;
    d_xbuf[idx] = c[0] * Wn[h] + c[1] * Wn[H_ + h] + c[2] * Wn[2 * H_ + h] + bn[h];
}

// e = concat(ev*Wev + bev, tour*Wec0 + best*Wec1 + bec), written SPLIT
__global__ void edge_embed_kernel(const float* __restrict__ ev,
                                  const float* __restrict__ tour,
                                  const float* __restrict__ btour,
                                  const float* __restrict__ Wev,
                                  const float* __restrict__ bev,
                                  const float* __restrict__ Wec,
                                  const float* __restrict__ bec) {
    int idx4 = blockIdx.x * blockDim.x + threadIdx.x;  // EN_/4
    int h4 = idx4 & 31;
    int edge = idx4 >> 5;
    int h0 = h4 * 4;
    float4 o;
    if (h0 < H2_) {
        float v = ev[edge];
        o.x = v * Wev[h0 + 0] + bev[h0 + 0];
        o.y = v * Wev[h0 + 1] + bev[h0 + 1];
        o.z = v * Wev[h0 + 2] + bev[h0 + 2];
        o.w = v * Wev[h0 + 3] + bev[h0 + 3];
    } else {
        float t = tour[edge], bt = btour[edge];
        int g = h0 - H2_;
        o.x = t * Wec[g + 0] + bt * Wec[H2_ + g + 0] + bec[g + 0];
        o.y = t * Wec[g + 1] + bt * Wec[H2_ + g + 1] + bec[g + 1];
        o.z = t * Wec[g + 2] + bt * Wec[H2_ + g + 2] + bec[g + 2];
        o.w = t * Wec[g + 3] + bt * Wec[H2_ + g + 3] + bec[g + 3];
    }
    uint2 hi, lo;
    split2(o.x, o.y, hi.x, lo.x);
    split2(o.z, o.w, hi.y, lo.y);
    reinterpret_cast<uint2*>(d_ehi)[idx4] = hi;
    reinterpret_cast<uint2*>(d_elo)[idx4] = lo;
}

// Combined per-layer prep: blocks 0-63 = Vex/Vnx/Unx gemm3; 64-191 = UeT split;
// block 192 = zero stats. (Keeps fused_edge_kernel as the 4th launch.)
__global__ void __launch_bounds__(128) prep_kernel(
        const float* __restrict__ Ue,
        const float* __restrict__ Ve, const float* __restrict__ bVe,
        const float* __restrict__ Vn, const float* __restrict__ bVn,
        const float* __restrict__ Un, const float* __restrict__ bUn) {
    int bid = blockIdx.x;
    int tid = threadIdx.x;
    if (bid >= 192) {
        for (int i = tid; i < 768; i += 128) d_stats[i] = 0.f;
        return;
    }
    if (bid >= 64) {
        int h = bid - 64;
        int k = tid;
        float f = Ue[k * H_ + h];
        __nv_bfloat16 hi = __float2bfloat16_rn(f);
        d_UeThi[h * H_ + k] = hi;
        d_UeTlo[h * H_ + k] = __float2bfloat16_rn(f - __bfloat162float(hi));
        return;
    }
    // gemm3 part
    __shared__ float xs[16 * H_];
    int h = tid;
    int r0 = bid * 16;
    {
        const float4* src = reinterpret_cast<const float4*>(d_xbuf + r0 * H_);
        float4* dst = reinterpret_cast<float4*>(xs);
#pragma unroll
        for (int t = 0; t < 4; ++t) dst[h + t * 128] = src[h + t * 128];
    }
    __syncthreads();
    float a0[16], a1[16], a2[16];
    {
        float v0 = bVe[h], v1 = bVn[h], v2 = bUn[h];
#pragma unroll
        for (int r = 0; r < 16; ++r) { a0[r] = v0; a1[r] = v1; a2[r] = v2; }
    }
    for (int k = 0; k < H_; k += 4) {
        float w0[4], w1[4], w2[4];
#pragma unroll
        for (int q = 0; q < 4; ++q) {
            w0[q] = Ve[(k + q) * H_ + h];
            w1[q] = Vn[(k + q) * H_ + h];
            w2[q] = Un[(k + q) * H_ + h];
        }
#pragma unroll
        for (int r = 0; r < 16; ++r) {
            float4 xv = *reinterpret_cast<const float4*>(xs + r * H_ + k);
            a0[r] += xv.x * w0[0] + xv.y * w0[1] + xv.z * w0[2] + xv.w * w0[3];
            a1[r] += xv.x * w1[0] + xv.y * w1[1] + xv.z * w1[2] + xv.w * w1[3];
            a2[r] += xv.x * w2[0] + xv.y * w2[1] + xv.z * w2[2] + xv.w * w2[3];
        }
    }
#pragma unroll
    for (int r = 0; r < 16; ++r) {
        d_Vex[(r0 + r) * H_ + h] = a0[r];
        d_Vnx[(r0 + r) * H_ + h] = a1[r];
        d_Unx[(r0 + r) * H_ + h] = a2[r];
    }
}

// ---------------------------------------------------------------------------
// Fused edge layer: cp.async double-buffered slabs (32 j), ldmatrix + mma.sync,
// 3-term bf16 hi/lo split. e arrives pre-split from global (no conversion).
// Smem: XOR-swizzled 256B rows (16B chunk c at c ^ (row&7)).
#define OFF_UHI  0          // 32768 (128 rows x 256B)
#define OFF_ULO  32768      // 32768
#define OFF_EB   65536      // 2 buffers x (hi 8192 + lo 8192) = 32768
#define OFF_BASE 98304      // 512
#define OFF_RED  98816      // 4096 (8 groups x 128 h)
#define SMEM_F   102912

__device__ __forceinline__ void fetch_slab(uint32_t smb, int buf,
                                           size_t erow_elem, int s, int tid) {
    // 1024 x 16B chunks: 2 planes x 32 rows x 16 chunks
#pragma unroll
    for (int t = 0; t < 4; ++t) {
        int idx = tid + t * 256;
        int plane = idx >> 9;
        int r = (idx >> 4) & 31;
        int c = idx & 15;
        const __nv_bfloat16* src =
            (plane ? d_elo : d_ehi) + erow_elem + (size_t)(s * 32 + r) * H_ + c * 8;
        uint32_t dst = smb + OFF_EB + buf * 16384 + plane * 8192 +
                       r * 256 + ((c ^ (r & 7)) << 4);
        CP16(dst, src);
    }
}

__global__ void __launch_bounds__(256, 2) fused_edge_kernel(
        const float* __restrict__ bUe, int write_e) {
    extern __shared__ char smc[];
    uint32_t smb = s2u(smc);
    int tid = threadIdx.x, w = tid >> 5, lane = tid & 31;
    int wj = w & 1, wh = w >> 1;
    int bi = blockIdx.x, b = bi >> 8;
    size_t erow = (size_t)bi * (V_ * H_);

    // prologue: U tiles (4096 chunks) + e slab 0, one commit group
#pragma unroll
    for (int t = 0; t < 16; ++t) {
        int idx = tid + t * 256;
        int plane = idx >> 11;
        int hrow = (idx >> 4) & 127;
        int c = idx & 15;
        const __nv_bfloat16* src =
            (plane ? d_UeTlo : d_UeThi) + hrow * H_ + c * 8;
        uint32_t dst = smb + (plane ? OFF_ULO : OFF_UHI) +
                       hrow * 256 + ((c ^ (hrow & 7)) << 4);
        CP16(dst, src);
    }
    fetch_slab(smb, 0, erow, 0, tid);
    CPCOMMIT();
    if (tid < H_)
        reinterpret_cast<float*>(smc + OFF_BASE)[tid] =
            bUe[tid] + d_Vex[bi * H_ + tid];

    const float* VexB = d_Vex + (size_t)b * V_ * H_;
    const float* VnxB = d_Vnx + (size_t)b * V_ * H_;
    float* etrow = d_etmp + erow;

    // per-thread fragment address components
    int arow = wj * 16 + (lane & 15);
    uint32_t a_base = smb + OFF_EB + arow * 256;   // + buf*16384 (+8192 lo)
    int a_hi4 = lane >> 4;                         // chunk half
    int amask = arow & 7;
    int brow0 = wh * 32 + ((lane >> 4) & 1) * 8 + (lane & 7);       // pair 0
    int bchalf = (lane >> 3) & 1;
    uint32_t b_base0 = smb + OFF_UHI + brow0 * 256;
    uint32_t b_base1 = b_base0 + 16 * 256;                           // pair 1
    int bmask0 = brow0 & 7, bmask1 = (brow0 + 16) & 7;

    // register accumulators across slabs
    float sN0[4], sN1[4], sD0[4], sD1[4], sS0[4], sS1[4], sQ0[4], sQ1[4];
#pragma unroll
    for (int t = 0; t < 4; ++t) {
        sN0[t] = sN1[t] = sD0[t] = sD1[t] = 0.f;
        sS0[t] = sS1[t] = sQ0[t] = sQ1[t] = 0.f;
    }

    for (int s = 0; s < 8; ++s) {
        if (s < 7) { fetch_slab(smb, (s + 1) & 1, erow, s + 1, tid); CPCOMMIT(); }
        if (s < 7) asm volatile("cp.async.wait_group 1;");
        else       asm volatile("cp.async.wait_group 0;");
        __syncthreads();

        uint32_t ebuf = a_base + (s & 1) * 16384;
        float acc[4][4];
#pragma unroll
        for (int t = 0; t < 4; ++t)
#pragma unroll
            for (int q = 0; q < 4; ++q) acc[t][q] = 0.f;

#pragma unroll
        for (int kk = 0; kk < 8; ++kk) {
            uint32_t ah[4], al[4];
            uint32_t aoff = (uint32_t)(((kk * 2 + a_hi4) ^ amask) << 4);
            ldsm4(ebuf + aoff, ah);
            ldsm4(ebuf + 8192 + aoff, al);
#pragma unroll
            for (int p = 0; p < 2; ++p) {
                uint32_t bh[4], bl[4];
                int bm = p ? bmask1 : bmask0;
                uint32_t bb = p ? b_base1 : b_base0;
                uint32_t boff = (uint32_t)(((kk * 2 + bchalf) ^ bm) << 4);
                ldsm4(bb + boff, bh);
                ldsm4(bb + 32768 + boff, bl);
                mma16816(acc[p * 2],     ah, bh[0], bh[1]);
                mma16816(acc[p * 2],     al, bh[0], bh[1]);
                mma16816(acc[p * 2],     ah, bl[0], bl[1]);
                mma16816(acc[p * 2 + 1], ah, bh[2], bh[3]);
                mma16816(acc[p * 2 + 1], al, bh[2], bh[3]);
                mma16816(acc[p * 2 + 1], ah, bl[2], bl[3]);
            }
        }

        // epilogue on fragments (accumulate into registers)
        int jr0 = s * 32 + wj * 16 + (lane >> 2);
        int jr1 = jr0 + 8;
#pragma unroll
        for (int t = 0; t < 4; ++t) {
            int h0 = wh * 32 + t * 8 + (lane & 3) * 2;
            float2 bse = *reinterpret_cast<const float2*>(smc + OFF_BASE + h0 * 4);
            float2 vx0 = *reinterpret_cast<const float2*>(VexB + jr0 * H_ + h0);
            float2 vx1 = *reinterpret_cast<const float2*>(VexB + jr1 * H_ + h0);
            float2 vn0 = *reinterpret_cast<const float2*>(VnxB + jr0 * H_ + h0);
            float2 vn1 = *reinterpret_cast<const float2*>(VnxB + jr1 * H_ + h0);
            float et00 = acc[t][0] + bse.x + vx0.x;
            float et01 = acc[t][1] + bse.y + vx0.y;
            float et10 = acc[t][2] + bse.x + vx1.x;
            float et11 = acc[t][3] + bse.y + vx1.y;
            float g00 = 1.f / (1.f + __expf(-et00));
            float g01 = 1.f / (1.f + __expf(-et01));
            float g10 = 1.f / (1.f + __expf(-et10));
            float g11 = 1.f / (1.f + __expf(-et11));
            sN0[t] += g00 * vn0.x + g10 * vn1.x;
            sN1[t] += g01 * vn0.y + g11 * vn1.y;
            sD0[t] += g00 + g10;
            sD1[t] += g01 + g11;
            if (write_e) {
                sS0[t] += et00 + et10;
                sS1[t] += et01 + et11;
                sQ0[t] += et00 * et00 + et10 * et10;
                sQ1[t] += et01 * et01 + et11 * et11;
                *reinterpret_cast<float2*>(etrow + (size_t)jr0 * H_ + h0) =
                    make_float2(et00, et01);
                *reinterpret_cast<float2*>(etrow + (size_t)jr1 * H_ + h0) =
                    make_float2(et10, et11);
            }
        }
        __syncthreads();
    }

    // final reduction over j-lanes (xor shuffles), then smem across wj groups
    float* red = reinterpret_cast<float*>(smc + OFF_RED);
#pragma unroll
    for (int t = 0; t < 4; ++t) {
#pragma unroll
        for (int o = 4; o < 32; o <<= 1) {
            sN0[t] += __shfl_xor_sync(0xffffffffu, sN0[t], o);
            sN1[t] += __shfl_xor_sync(0xffffffffu, sN1[t], o);
            sD0[t] += __shfl_xor_sync(0xffffffffu, sD0[t], o);
            sD1[t] += __shfl_xor_sync(0xffffffffu, sD1[t], o);
        }
        if (write_e) {
#pragma unroll
            for (int o = 4; o < 32; o <<= 1) {
                sS0[t] += __shfl_xor_sync(0xffffffffu, sS0[t], o);
                sS1[t] += __shfl_xor_sync(0xffffffffu, sS1[t], o);
                sQ0[t] += __shfl_xor_sync(0xffffffffu, sQ0[t], o);
                sQ1[t] += __shfl_xor_sync(0xffffffffu, sQ1[t], o);
            }
        }
        if (lane < 4) {
            int h = wh * 32 + t * 8 + lane * 2;
            red[(0 * 2 + wj) * 128 + h]     = sN0[t];
            red[(0 * 2 + wj) * 128 + h + 1] = sN1[t];
            red[(1 * 2 + wj) * 128 + h]     = sD0[t];
            red[(1 * 2 + wj) * 128 + h + 1] = sD1[t];
            red[(2 * 2 + wj) * 128 + h]     = sS0[t];
            red[(2 * 2 + wj) * 128 + h + 1] = sS1[t];
            red[(3 * 2 + wj) * 128 + h]     = sQ0[t];
            red[(3 * 2 + wj) * 128 + h + 1] = sQ1[t];
        }
    }
    __syncthreads();
    if (tid < H_) {
        float n = red[tid] + red[128 + tid];
        float d = red[256 + tid] + red[384 + tid];
        float aggv = n / (d + 1e-20f);
        float xt = aggv + d_Unx[bi * H_ + tid];
        d_xtmp[bi * H_ + tid] = xt;
        atomicAdd(&d_stats[256 + tid], xt);
        atomicAdd(&d_stats[384 + tid], xt * xt);
        if (write_e) {
            atomicAdd(&d_stats[tid],       red[512 + tid] + red[640 + tid]);
            atomicAdd(&d_stats[128 + tid], red[768 + tid] + red[896 + tid]);
        }
    }
}

// x += relu(bn(x_tmp))
__global__ void xupdate_kernel(const float* __restrict__ gx,
                               const float* __restrict__ bx) {
    int idx = blockIdx.x * blockDim.x + threadIdx.x;
    int h = idx & (H_ - 1);
    const float inv = 1.f / (float)BV_;
    float mu  = d_stats[256 + h] * inv;
    float var = d_stats[384 + h] * inv - mu * mu;
    float t = gx[h] * (d_xtmp[idx] - mu) * rsqrtf(var + 1e-5f) + bx[h];
    d_xbuf[idx] += fmaxf(t, 0.f);
}

// Turn e sum/sumsq into scale/shift (slots 512/640)
__global__ void finalize_e_kernel(const float* __restrict__ ge,
                                  const float* __restrict__ be) {
    int h = threadIdx.x;
    const float inv = 1.f / (float)(B_ * V_ * V_);
    float mu  = d_stats[h] * inv;
    float var = d_stats[128 + h] * inv - mu * mu;
    float sc = ge[h] * rsqrtf(var + 1e-5f);
    d_stats[512 + h] = sc;
    d_stats[640 + h] = be[h] - mu * sc;
}

// e += relu(e_tmp*scale + shift), in split representation
__global__ void eupdate_kernel() {
    int idx4 = blockIdx.x * blockDim.x + threadIdx.x;  // EN_/4
    int h4 = idx4 & 31;
    int h0 = h4 * 4;
    uint2 hi = reinterpret_cast<const uint2*>(d_ehi)[idx4];
    uint2 lo = reinterpret_cast<const uint2*>(d_elo)[idx4];
    float4 et = reinterpret_cast<const float4*>(d_etmp)[idx4];
    float4 sc = *reinterpret_cast<const float4*>(d_stats + 512 + h0);
    float4 sh = *reinterpret_cast<const float4*>(d_stats + 640 + h0);
    float2 hxy = up_bf2(hi.x), hzw = up_bf2(hi.y);
    float2 lxy = up_bf2(lo.x), lzw = up_bf2(lo.y);
    float vx = hxy.x + lxy.x + fmaxf(et.x * sc.x + sh.x, 0.f);
    float vy = hxy.y + lxy.y + fmaxf(et.y * sc.y + sh.y, 0.f);
    float vz = hzw.x + lzw.x + fmaxf(et.z * sc.z + sh.z, 0.f);
    float vw = hzw.y + lzw.y + fmaxf(et.w * sc.w + sh.w, 0.f);
    uint2 nhi, nlo;
    split2(vx, vy, nhi.x, nlo.x);
    split2(vz, vw, nhi.y, nlo.y);
    reinterpret_cast<uint2*>(d_ehi)[idx4] = nhi;
    reinterpret_cast<uint2*>(d_elo)[idx4] = nlo;
}

__global__ void zero_out_kernel(float* out) {
    if (threadIdx.x < B_) out[threadIdx.x] = 0.f;
}

// per (b,v): h = relu(x@W1+b1); v = h@W2 + b2; out[b] += v/V
__global__ void readout_kernel(const float* __restrict__ W1,
                               const float* __restrict__ b1,
                               const float* __restrict__ W2,
                               const float* __restrict__ b2,
                               float* __restrict__ out) {
    __shared__ float xs[H_];
    __shared__ float wred[4];
    int row = blockIdx.x;
    int tid = threadIdx.x;
    xs[tid] = d_xbuf[row * H_ + tid];
    __syncthreads();
    float acc = b1[tid];
#pragma unroll 8
    for (int k = 0; k < H_; ++k) acc += xs[k] * W1[k * H_ + tid];
    float v = fmaxf(acc, 0.f) * W2[tid];
#pragma unroll
    for (int o = 16; o > 0; o >>= 1) v += __shfl_down_sync(0xffffffffu, v, o);
    if ((tid & 31) == 0) wred[tid >> 5] = v;
    __syncthreads();
    if (tid == 0) {
        float s = wred[0] + wred[1] + wred[2] + wred[3] + b2[0];
        atomicAdd(&out[row >> 8], s * (1.f / (float)V_));
    }
}

// ---------------------------------------------------------------------------
extern "C" void kernel_launch(void* const* d_in, const int* in_sizes, int n_in,
                              void* d_out, int out_size) {
    const float* xev   = (const float*)d_in[1];
    const float* coord = (const float*)d_in[2];
    const float* tour  = (const float*)d_in[3];
    const float* btour = (const float*)d_in[4];
    const float* Wn    = (const float*)d_in[5];
    const float* bn    = (const float*)d_in[6];
    const float* Wev   = (const float*)d_in[7];
    const float* bev   = (const float*)d_in[8];
    const float* Wec   = (const float*)d_in[9];
    const float* bec   = (const float*)d_in[10];
    const float* Ue    = (const float*)d_in[11];
    const float* bUe   = (const float*)d_in[12];
    const float* Ve    = (const float*)d_in[13];
    const float* bVe   = (const float*)d_in[14];
    const float* Un    = (const float*)d_in[15];
    const float* bUn   = (const float*)d_in[16];
    const float* Vn    = (const float*)d_in[17];
    const float* bVn   = (const float*)d_in[18];
    const float* ge    = (const float*)d_in[19];
    const float* be    = (const float*)d_in[20];
    const float* gx    = (const float*)d_in[21];
    const float* bx    = (const float*)d_in[22];
    const float* W1    = (const float*)d_in[23];
    const float* b1    = (const float*)d_in[24];
    const float* W2    = (const float*)d_in[25];
    const float* b2    = (const float*)d_in[26];
    float* out = (float*)d_out;

    cudaFuncSetAttribute(fused_edge_kernel,
                         cudaFuncAttributeMaxDynamicSharedMemorySize, SMEM_F);

    node_embed_kernel<<<XN_ / 256, 256>>>(coord, Wn, bn);
    edge_embed_kernel<<<EN_ / 4 / 256, 256>>>(xev, tour, btour, Wev, bev, Wec, bec);

    for (int l = 0; l < L_; ++l) {
        prep_kernel<<<193, 128>>>(Ue + l * H_ * H_,
                                  Ve + l * H_ * H_, bVe + l * H_,
                                  Vn + l * H_ * H_, bVn + l * H_,
                                  Un + l * H_ * H_, bUn + l * H_);
        int write_e = (l < L_ - 1) ? 1 : 0;
        fused_edge_kernel<<<BV_, 256, SMEM_F>>>(bUe + l * H_, write_e);
        xupdate_kernel<<<XN_ / 256, 256>>>(gx + l * H_, bx + l * H_);
        if (write_e) {
            finalize_e_kernel<<<1, 128>>>(ge + l * H_, be + l * H_);
            eupdate_kernel<<<EN_ / 4 / 256, 256>>>();
        }
    }

    zero_out_kernel<<<1, 32>>>(out);
    readout_kernel<<<BV_, H_>>>(W1, b1, W2, b2, out);
}